// round 17
// baseline (speedup 1.0000x reference)
#include <cuda_runtime.h>
#include <cstdint>

// SpectralConv1d via pruned cas-FFT (R16 pipeline, measured best 94.7us).
// R17 delta: inverse twiddles for the conflicted levels (t=5,4,2,1) come from
// compacted unit-stride tables g_CT (6.9KB), killing 2/4-way LDS bank
// conflicts; t=3,t=0 (already conflict-free) keep using cas_s.

#define NN     4096
#define MODES  64
#define CH     128
#define ROWS   8192

#define SQ2   1.41421356237309515f
#define C256  1.30656296487637653f   // cas(pi/8)
#define C1280 0.54119610014619698f   // cas(5pi/8)

__device__ __align__(16) float g_CAS[2048];   // cas(2*pi*j/4096)
__device__ __align__(16) float g_CT[1792];    // [c1:1024][c2:512][c4:128][c5:64][pad]
__device__ __align__(16) float g_OM[2048];    // omega[k<64][q<32]
__device__ float g_Y[MODES * ROWS];           // [m][row]
__device__ float g_Z[MODES * ROWS];           // [m][row]  (already /4096)
__device__ float g_We[MODES * CH * CH];       // [m][i][o]
__device__ float g_Wo[MODES * CH * CH];       // [m][i][o]

// compacted table offsets within g_CT / casT
#define CT1 0
#define CT2 1024
#define CT4 1536
#define CT5 1664

// ---------------- merged build: blocks 0-127 = wewo, 128-159 = tables ----------------
__global__ __launch_bounds__(256) void build_all_kernel(const float* __restrict__ w1) {
    __shared__ float tile[64 * 129];
    int b = blockIdx.x, tid = threadIdx.x;

    if (b < 128) {
        int i = b;
        const float* src = w1 + (size_t)i * 8192;   // [o][m], m fast
        for (int idx = tid; idx < 8192; idx += 256) {
            int o = idx >> 6, m = idx & 63;
            tile[m * 129 + o] = src[idx];
        }
        __syncthreads();
        for (int j = tid; j < 8192; j += 256) {
            int m = j >> 7, o = j & 127;
            int mn = (MODES - m) & 63;
            float a = tile[m * 129 + o];
            float bb = tile[mn * 129 + o];
            size_t d = (size_t)m * 16384 + (size_t)i * 128 + o;
            g_We[d] = 0.5f * (a + bb);
            g_Wo[d] = 0.5f * (a - bb);
        }
    } else {
        int j = (b - 128) * 256 + tid;   // 0..8191
        if (j < 2048) {
            float s, c;
            sincospif((float)j * (1.0f / 2048.0f), &s, &c);
            g_CAS[j] = c + s;
        } else if (j < 4096) {
            int idx = j - 2048;
            int k = idx >> 5, q = idx & 31;
            float w = 1.0f;
            #pragma unroll
            for (int t = 0; t < 5; t++) {
                if ((q >> t) & 1) {
                    float s, c;
                    sincospif((float)(k << t) * (1.0f / 2048.0f), &s, &c);
                    w *= (c + s);
                }
            }
            g_OM[idx] = w;
        } else if (j < 5888) {
            int i = j - 4096;
            int src;
            if      (i < 1024) src = i << 1;              // c1: g_CAS[2i]
            else if (i < 1536) src = (i - 1024) << 2;     // c2: g_CAS[4i]
            else if (i < 1664) src = (i - 1536) << 4;     // c4: g_CAS[16i]
            else               src = (i - 1664) << 5;     // c5: g_CAS[32i]
            float s, c;
            sincospif((float)src * (1.0f / 2048.0f), &s, &c);
            g_CT[i] = c + s;
        }
    }
}

__device__ __forceinline__ int brev4(int r) {
    return ((r & 1) << 3) | ((r & 2) << 1) | ((r & 4) >> 1) | ((r & 8) >> 3);
}

// ---------------- forward (unchanged) ----------------
__global__ __launch_bounds__(256, 6) void forward_kernel(const float* __restrict__ x) {
    __shared__ float buf[4096];
    __shared__ float cas32s[64];
    int h = threadIdx.x, row = blockIdx.x;
    int lane = h & 31, wrp = h >> 5;

    if (h < 64) cas32s[h] = g_CAS[h << 5];

    const float* xr = x + (size_t)row * NN;
    float v[16];
    #pragma unroll
    for (int r = 0; r < 16; r++) v[r] = xr[h + (r << 8)];

    float om[8];
    #pragma unroll
    for (int c = 0; c < 8; c++) om[c] = g_OM[((wrp + (c << 3)) << 5) + lane];

    #pragma unroll
    for (int r = 0; r < 8; r++) { float a = v[r], b = v[r + 8]; v[r] = a + b; v[r + 8] = a - b; }
    #pragma unroll
    for (int r = 0; r < 16; r++) if (!(r & 4)) { float a = v[r], b = v[r + 4]; v[r] = a + b; v[r + 4] = a - b; }
    {
        const float TW9[4] = {1.f, SQ2, 1.f, 0.f};
        #pragma unroll
        for (int r = 0; r < 16; r++) if (!(r & 2)) {
            int kt = ((r >> 3) & 1) | (((r >> 2) & 1) << 1);
            float w = TW9[kt], a = v[r], b = v[r + 2];
            v[r] = fmaf(w, b, a); v[r + 2] = fmaf(-w, b, a);
        }
    }
    {
        const float TW8[8] = {1.f, C256, SQ2, C256, 1.f, C1280, 0.f, -C1280};
        #pragma unroll
        for (int r = 0; r < 16; r += 2) {
            int kt = ((r >> 3) & 1) | (((r >> 2) & 1) << 1) | (((r >> 1) & 1) << 2);
            float w = TW8[kt], a = v[r], b = v[r + 1];
            v[r] = fmaf(w, b, a); v[r + 1] = fmaf(-w, b, a);
        }
    }
    #pragma unroll
    for (int r = 0; r < 16; r++) buf[h + (brev4(r) << 8)] = v[r];
    __syncthreads();

    int hi3 = wrp;
    int base = (h & 31) + (hi3 << 8);
    float u[16];
    #pragma unroll
    for (int r = 0; r < 16; r++) u[r] = buf[base + ((r & 7) << 5) + ((r & 8) << 8)];
    #pragma unroll
    for (int r = 0; r < 16; r++) if (!(r & 4)) {
        float w = cas32s[(hi3 + (r & 8)) << 2];
        float a = u[r], b = u[r + 4];
        u[r] = fmaf(w, b, a); u[r + 4] = fmaf(-w, b, a);
    }
    #pragma unroll
    for (int r = 0; r < 16; r++) if (!(r & 2)) {
        float w = cas32s[(hi3 + (r & 8) + ((r & 4) << 2)) << 1];
        float a = u[r], b = u[r + 2];
        u[r] = fmaf(w, b, a); u[r + 2] = fmaf(-w, b, a);
    }
    #pragma unroll
    for (int r = 0; r < 16; r += 2) {
        float w = cas32s[hi3 + (r & 8) + ((r & 4) << 2) + ((r & 2) << 4)];
        u[r] = fmaf(w, u[r + 1], u[r]);
    }

    float val[8];
    #pragma unroll
    for (int c = 0; c < 8; c++) {
        int j = ((c & 1) << 2) | (c & 2) | ((c & 4) >> 2);
        val[c] = om[c] * u[2 * j];
    }
    bool b4 = (lane & 16) != 0, b3 = (lane & 8) != 0, b2 = (lane & 4) != 0;
    float a4[4];
    #pragma unroll
    for (int c = 0; c < 4; c++) {
        float keep = b4 ? val[c + 4] : val[c];
        float give = b4 ? val[c] : val[c + 4];
        a4[c] = keep + __shfl_xor_sync(0xffffffffu, give, 16);
    }
    float a2[2];
    #pragma unroll
    for (int c = 0; c < 2; c++) {
        float keep = b3 ? a4[c + 2] : a4[c];
        float give = b3 ? a4[c] : a4[c + 2];
        a2[c] = keep + __shfl_xor_sync(0xffffffffu, give, 8);
    }
    float e;
    {
        float keep = b2 ? a2[1] : a2[0];
        float give = b2 ? a2[0] : a2[1];
        e = keep + __shfl_xor_sync(0xffffffffu, give, 4);
    }
    e += __shfl_xor_sync(0xffffffffu, e, 2);
    e += __shfl_xor_sync(0xffffffffu, e, 1);
    if ((lane & 3) == 0) g_Y[(wrp + ((lane >> 2) << 3)) * ROWS + row] = e;
}

// ---------------- mix (unchanged) ----------------
__device__ __forceinline__ void cp16(uint32_t daddr, const void* gptr) {
    asm volatile("cp.async.cg.shared.global [%0], [%1], 16;" :: "r"(daddr), "l"(gptr));
}

__global__ __launch_bounds__(128) void mix_kernel() {
    __shared__ float Ys[8 * CH];
    __shared__ float Yn[8 * CH];
    extern __shared__ float4 Wbuf[];

    int m = blockIdx.x >> 3, g = blockIdx.x & 7;
    int mn = (MODES - m) & 63;
    int tid = threadIdx.x;
    int oq = tid & 31, bg = tid >> 5;

    const float* We = g_We + (size_t)m * 16384;
    const float* Wo = g_Wo + (size_t)m * 16384;
    uint32_t wb = (uint32_t)__cvta_generic_to_shared(Wbuf);

    #define ISSUE_CHUNK(c, s) do {                                              \
        const float4* se = (const float4*)(We + (c) * 2048);                    \
        const float4* so = (const float4*)(Wo + (c) * 2048);                    \
        uint32_t de = wb + (uint32_t)((s) * 2 + 0) * 8192;                      \
        uint32_t dn = wb + (uint32_t)((s) * 2 + 1) * 8192;                      \
        _Pragma("unroll")                                                       \
        for (int jj = 0; jj < 4; jj++) {                                        \
            int idx = tid + jj * 128;                                           \
            cp16(de + idx * 16, se + idx);                                      \
            cp16(dn + idx * 16, so + idx);                                      \
        }                                                                       \
        asm volatile("cp.async.commit_group;" ::: "memory");                    \
    } while (0)

    ISSUE_CHUNK(0, 0);
    ISSUE_CHUNK(1, 1);

    for (int idx = tid; idx < 1024; idx += 128) {
        Ys[idx] = g_Y[m * ROWS + g * 1024 + idx];
        Yn[idx] = g_Y[mn * ROWS + g * 1024 + idx];
    }

    float4 a0 = {0,0,0,0}, a1 = {0,0,0,0};
    int l0 = 2 * bg, l1 = l0 + 1;

    #pragma unroll 1
    for (int c = 0; c < 8; c++) {
        if (c < 7) asm volatile("cp.async.wait_group 1;" ::: "memory");
        else       asm volatile("cp.async.wait_group 0;" ::: "memory");
        __syncthreads();

        const float4* Wef = &Wbuf[(size_t)((c & 1) * 2 + 0) * 512];
        const float4* Wof = &Wbuf[(size_t)((c & 1) * 2 + 1) * 512];
        #pragma unroll
        for (int ii = 0; ii < 16; ii++) {
            float4 we = Wef[ii * 32 + oq];
            float4 wo = Wof[ii * 32 + oq];
            int i = c * 16 + ii;
            float y0 = Ys[l0 * CH + i], z0 = Yn[l0 * CH + i];
            float y1 = Ys[l1 * CH + i], z1 = Yn[l1 * CH + i];
            a0.x = fmaf(y0, we.x, a0.x); a0.x = fmaf(z0, wo.x, a0.x);
            a0.y = fmaf(y0, we.y, a0.y); a0.y = fmaf(z0, wo.y, a0.y);
            a0.z = fmaf(y0, we.z, a0.z); a0.z = fmaf(z0, wo.z, a0.z);
            a0.w = fmaf(y0, we.w, a0.w); a0.w = fmaf(z0, wo.w, a0.w);
            a1.x = fmaf(y1, we.x, a1.x); a1.x = fmaf(z1, wo.x, a1.x);
            a1.y = fmaf(y1, we.y, a1.y); a1.y = fmaf(z1, wo.y, a1.y);
            a1.z = fmaf(y1, we.z, a1.z); a1.z = fmaf(z1, wo.z, a1.z);
            a1.w = fmaf(y1, we.w, a1.w); a1.w = fmaf(z1, wo.w, a1.w);
        }
        __syncthreads();
        if (c < 6) ISSUE_CHUNK(c + 2, c & 1);
    }

    const float inv = 1.0f / 4096.0f;
    float4* Z4 = (float4*)g_Z;
    float4 s0 = make_float4(a0.x * inv, a0.y * inv, a0.z * inv, a0.w * inv);
    float4 s1 = make_float4(a1.x * inv, a1.y * inv, a1.z * inv, a1.w * inv);
    int b0 = g * 8 + l0;
    Z4[(size_t)m * 2048 + (size_t)b0 * 32 + oq]       = s0;
    Z4[(size_t)m * 2048 + (size_t)(b0 + 1) * 32 + oq] = s1;
    #undef ISSUE_CHUNK
}

// ---------------- inverse (compacted unit-stride twiddle tables) ----------------
__global__ __launch_bounds__(256, 6) void inverse_kernel(float* __restrict__ out) {
    __shared__ float buf[4096];
    __shared__ __align__(16) float cas_s[2048];
    __shared__ __align__(16) float casT[1792];
    __shared__ float zb[64];
    int h = threadIdx.x, row = blockIdx.x;

    {
        float4* c4 = (float4*)cas_s;
        const float4* s4 = (const float4*)g_CAS;
        c4[h] = s4[h];
        c4[h + 256] = s4[h + 256];
        float4* t4 = (float4*)casT;
        const float4* g4 = (const float4*)g_CT;
        t4[h] = g4[h];
        if (h < 192) t4[256 + h] = g4[256 + h];
    }
    if (h < 64) zb[h] = g_Z[(size_t)h * ROWS + row];   // [m][row] layout
    __syncthreads();

    float v[16];
    #pragma unroll
    for (int r = 0; r < 16; r++) v[r] = zb[(h & 7) + ((r & 7) << 3)];

    int hk = (h >> 3) & 31;
    // t=5: conflict-free via c5
    #pragma unroll
    for (int r = 0; r < 16; r++) if (!(r & 4)) {
        float w = casT[CT5 + hk + ((r & 8) << 2)];
        float a = v[r], b = v[r + 4];
        v[r] = fmaf(w, b, a); v[r + 4] = fmaf(-w, b, a);
    }
    // t=4: conflict-free via c4
    #pragma unroll
    for (int r = 0; r < 16; r++) if (!(r & 2)) {
        float w = casT[CT4 + hk + ((r & 8) << 2) + ((r & 4) << 4)];
        float a = v[r], b = v[r + 2];
        v[r] = fmaf(w, b, a); v[r + 2] = fmaf(-w, b, a);
    }
    // t=3: already conflict-free in cas_s
    #pragma unroll
    for (int r = 0; r < 16; r += 2) {
        float w = cas_s[(hk + ((r & 8) << 2) + ((r & 4) << 4) + ((r & 2) << 6)) << 3];
        float a = v[r], b = v[r + 1];
        v[r] = fmaf(w, b, a); v[r + 1] = fmaf(-w, b, a);
    }

    #pragma unroll
    for (int r = 0; r < 16; r++) {
        int a = h + (brev4(r) << 8);
        buf[a ^ ((a >> 5) & 7)] = v[r];
    }
    __syncthreads();
    #pragma unroll
    for (int r = 0; r < 16; r++) {
        int a = (r & 7) + (h << 3) + ((r & 8) << 8);
        v[r] = buf[a ^ ((a >> 5) & 7)];
    }

    // t=2: conflict-free via c2
    #pragma unroll
    for (int r = 0; r < 16; r++) if (!(r & 4)) {
        float w = casT[CT2 + h + ((r & 8) << 5)];
        float a = v[r], b = v[r + 4];
        v[r] = fmaf(w, b, a); v[r + 4] = fmaf(-w, b, a);
    }
    // t=1: conflict-free via c1
    #pragma unroll
    for (int r = 0; r < 16; r++) if (!(r & 2)) {
        float w = casT[CT1 + h + ((r & 8) << 5) + ((r & 4) << 7)];
        float a = v[r], b = v[r + 2];
        v[r] = fmaf(w, b, a); v[r + 2] = fmaf(-w, b, a);
    }
    // t=0: already conflict-free in cas_s
    #pragma unroll
    for (int r = 0; r < 16; r += 2) {
        float w = cas_s[h + ((r & 8) << 5) + ((r & 4) << 7) + ((r & 2) << 9)];
        float a = v[r], b = v[r + 1];
        v[r] = fmaf(w, b, a); v[r + 1] = fmaf(-w, b, a);
    }

    // direct coalesced streaming stores (output never re-read)
    float* orow = out + (size_t)row * NN;
    #pragma unroll
    for (int r = 0; r < 16; r++) __stcs(&orow[h + (brev4(r) << 8)], v[r]);
}

extern "C" void kernel_launch(void* const* d_in, const int* in_sizes, int n_in,
                              void* d_out, int out_size) {
    const float* x  = (const float*)d_in[0];
    const float* w1 = (const float*)d_in[1];
    float* out = (float*)d_out;

    build_all_kernel<<<160, 256>>>(w1);          // launch 0
    forward_kernel<<<ROWS, 256>>>(x);            // launch 1
    mix_kernel<<<MODES * 8, 128, 32768>>>();     // launch 2
    inverse_kernel<<<ROWS, 256>>>(out);          // launch 3  <- ncu target
}